// round 15
// baseline (speedup 1.0000x reference)
#include <cuda_runtime.h>
#include <cuda_fp16.h>
#include <math.h>
#include <stdint.h>

#define Hh 256
#define NMAX 262144
#define BMAX 4096

// ---------------- device scratch (no allocations allowed) ----------------
__device__ int    d_starts[BMAX + 1];
__device__ float  d_gates[BMAX * 1024];
__device__ float  d_c0[BMAX * 256];
__device__ float  d_c1[BMAX * 256];
__device__ __half d_nodesh[(size_t)NMAX * 256];   // fp16 copy of nodes
// fp16 operands
__device__ __half d_X0[BMAX * 768];          // [q_star(512)|h0(256)]
__device__ __half d_X1[BMAX * 512];          // [h0(256)|h1(256)]
__device__ __half d_W0[1024 * 768];          // [Wih0|Whh0]
__device__ __half d_W1[1024 * 512];          // [Wih1|Whh1]
__device__ float  d_b0[1024], d_b1[1024];

// ---------------- small helpers ----------------
__device__ __forceinline__ uint32_t smem_u32(const void* p) {
    uint32_t a;
    asm("{ .reg .u64 t; cvta.to.shared.u64 t, %1; cvt.u32.u64 %0, t; }" : "=r"(a) : "l"(p));
    return a;
}
__device__ __forceinline__ void cp16(uint32_t dst, const void* src) {
    asm volatile("cp.async.cg.shared.global [%0], [%1], 16;" :: "r"(dst), "l"(src));
}
#define CP_COMMIT() asm volatile("cp.async.commit_group;" ::: "memory")
#define CP_WAIT1()  asm volatile("cp.async.wait_group 1;" ::: "memory")
#define CP_WAIT0()  asm volatile("cp.async.wait_group 0;" ::: "memory")

__device__ __forceinline__ void ldsm4(uint32_t* r, uint32_t addr) {
    asm volatile("ldmatrix.sync.aligned.m8n8.x4.shared.b16 {%0,%1,%2,%3}, [%4];"
                 : "=r"(r[0]), "=r"(r[1]), "=r"(r[2]), "=r"(r[3]) : "r"(addr));
}
__device__ __forceinline__ void mma16816(float* c, const uint32_t* a, const uint32_t* b) {
    asm volatile(
        "mma.sync.aligned.m16n8k16.row.col.f32.f16.f16.f32 "
        "{%0,%1,%2,%3},{%4,%5,%6,%7},{%8,%9},{%0,%1,%2,%3};"
        : "+f"(c[0]), "+f"(c[1]), "+f"(c[2]), "+f"(c[3])
        : "r"(a[0]), "r"(a[1]), "r"(a[2]), "r"(a[3]), "r"(b[0]), "r"(b[1]));
}

// ---------------- starts (with inline graph_id dtype sniff) ----------------
__global__ void starts_kernel(const int* p, int N, int B) {
    int g = blockIdx.x * blockDim.x + threadIdx.x;
    if (g > B) return;
    int is64 = 1;
    for (int j = 0; j < 8; j++) {
        int idx = N - 1 - 2 * j;
        if (idx < 1) break;
        if ((idx & 1) == 0) idx--;
        if (idx >= 1 && p[idx] != 0) is64 = 0;
    }
    const long long* p64 = (const long long*)p;
    int lo = 0, hi = N;
    while (lo < hi) {
        int mid = (lo + hi) >> 1;
        int v = is64 ? (int)p64[mid] : p[mid];
        if (v < g) lo = mid + 1; else hi = mid;
    }
    d_starts[g] = lo;
}

// ---------------- pack weights (fp16) + summed biases + c-state init ----------------
__global__ void pack_kernel(const float* __restrict__ Wih0, const float* __restrict__ Whh0,
                            const float* __restrict__ bih0, const float* __restrict__ bhh0,
                            const float* __restrict__ Wih1, const float* __restrict__ Whh1,
                            const float* __restrict__ bih1, const float* __restrict__ bhh1,
                            int B) {
    int i = blockIdx.x * blockDim.x + threadIdx.x;
    if (i < 1024 * 768) {
        int j = i / 768, k = i % 768;
        float v = (k < 512) ? Wih0[j * 512 + k] : Whh0[j * 256 + (k - 512)];
        d_W0[i] = __float2half_rn(v);
    }
    if (i < 1024 * 512) {
        int j = i / 512, k = i % 512;
        float v = (k < 256) ? Wih1[j * 256 + k] : Whh1[j * 256 + (k - 256)];
        d_W1[i] = __float2half_rn(v);
    }
    if (i < 1024) {
        d_b0[i] = bih0[i] + bhh0[i];
        d_b1[i] = bih1[i] + bhh1[i];
    }
    if (i < B * 256) { d_c0[i] = 0.f; d_c1[i] = 0.f; }
}

// ---------------- iteration 0: convert nodes->fp16 AND compute mean readout ----
__global__ void convert_mean_kernel(const float* __restrict__ nodes) {
    int g = blockIdx.x;
    int s = d_starts[g], en = d_starts[g + 1];
    int len = en - s;
    __shared__ float vsum[8][256];
    int tid = threadIdx.x, lane = tid & 31, w = tid >> 5;

    float v[8];
    #pragma unroll
    for (int j = 0; j < 8; j++) v[j] = 0.f;

    for (int n = s + w; n < en; n += 8) {
        const float4* rp = (const float4*)(nodes + (size_t)n * 256);
        float4 a = rp[2 * lane], b = rp[2 * lane + 1];
        __half2 h0 = __floats2half2_rn(a.x, a.y);
        __half2 h1 = __floats2half2_rn(a.z, a.w);
        __half2 h2 = __floats2half2_rn(b.x, b.y);
        __half2 h3 = __floats2half2_rn(b.z, b.w);
        uint4 pk;
        pk.x = *(uint32_t*)&h0; pk.y = *(uint32_t*)&h1;
        pk.z = *(uint32_t*)&h2; pk.w = *(uint32_t*)&h3;
        ((uint4*)(d_nodesh + (size_t)n * 256))[lane] = pk;
        v[0] += a.x; v[1] += a.y; v[2] += a.z; v[3] += a.w;
        v[4] += b.x; v[5] += b.y; v[6] += b.z; v[7] += b.w;
    }
    {
        float4* dst = (float4*)&vsum[w][8 * lane];
        dst[0] = make_float4(v[0], v[1], v[2], v[3]);
        dst[1] = make_float4(v[4], v[5], v[6], v[7]);
    }
    __syncthreads();

    float inv = (len > 0) ? 1.f / (float)len : 0.f;
    float acc = 0.f;
    #pragma unroll
    for (int i = 0; i < 8; i++) acc += vsum[i][tid];
    acc *= inv;

    d_X0[(size_t)g * 768 + tid] = __float2half_rn(0.f);
    d_X0[(size_t)g * 768 + 256 + tid] = __float2half_rn(acc);
}

// ---------------- attention (iters 1..5): fused act1 prologue + online softmax ----
__global__ void attention_kernel(float* __restrict__ dout, int final_iter) {
    int g = blockIdx.x;
    int s = d_starts[g], en = d_starts[g + 1];
    __shared__ float qs[256];
    __shared__ float vsum[8][256];
    __shared__ float wmx[8], wsx[8], wscale[8];
    __shared__ float s_inv;
    int tid = threadIdx.x, lane = tid & 31, w = tid >> 5;

    {
        const float* gr = d_gates + (size_t)g * 1024;
        float gi = gr[tid]       + d_b1[tid];
        float gf = gr[tid + 256] + d_b1[tid + 256];
        float gg = gr[tid + 512] + d_b1[tid + 512];
        float go = gr[tid + 768] + d_b1[tid + 768];
        float si = 1.f / (1.f + expf(-gi));
        float sf = 1.f / (1.f + expf(-gf));
        float tg = tanhf(gg);
        float so = 1.f / (1.f + expf(-go));
        size_t ci = (size_t)g * 256 + tid;
        float cn = sf * d_c1[ci] + si * tg;
        d_c1[ci] = cn;
        float hn = so * tanhf(cn);
        qs[tid] = hn;
        d_X1[(size_t)g * 512 + 256 + tid] = __float2half_rn(hn);
    }
    __syncthreads();

    float qv[8];
    #pragma unroll
    for (int j = 0; j < 8; j++) qv[j] = qs[8 * lane + j];

    float m = -3.4e38f, ssum = 0.f;
    float v[8];
    #pragma unroll
    for (int j = 0; j < 8; j++) v[j] = 0.f;

    int n = s + w;
    for (; n + 8 < en; n += 16) {
        uint4 p1 = ((const uint4*)(d_nodesh + (size_t)n * 256))[lane];
        uint4 p2 = ((const uint4*)(d_nodesh + (size_t)(n + 8) * 256))[lane];
        float2 a0 = __half22float2(*(__half2*)&p1.x);
        float2 a1 = __half22float2(*(__half2*)&p1.y);
        float2 a2 = __half22float2(*(__half2*)&p1.z);
        float2 a3 = __half22float2(*(__half2*)&p1.w);
        float2 b0 = __half22float2(*(__half2*)&p2.x);
        float2 b1 = __half22float2(*(__half2*)&p2.y);
        float2 b2 = __half22float2(*(__half2*)&p2.z);
        float2 b3 = __half22float2(*(__half2*)&p2.w);
        float x1[8] = {a0.x, a0.y, a1.x, a1.y, a2.x, a2.y, a3.x, a3.y};
        float x2[8] = {b0.x, b0.y, b1.x, b1.y, b2.x, b2.y, b3.x, b3.y};

        float d1 = 0.f, d2 = 0.f;
        #pragma unroll
        for (int j = 0; j < 8; j++) {
            d1 = fmaf(x1[j], qv[j], d1);
            d2 = fmaf(x2[j], qv[j], d2);
        }
        #pragma unroll
        for (int o = 16; o; o >>= 1) {
            d1 += __shfl_xor_sync(0xffffffffu, d1, o);
            d2 += __shfl_xor_sync(0xffffffffu, d2, o);
        }

        float mn = fmaxf(m, fmaxf(d1, d2));
        float scale = __expf(m - mn);
        float e1 = __expf(d1 - mn);
        float e2 = __expf(d2 - mn);
        ssum = ssum * scale + e1 + e2;
        #pragma unroll
        for (int j = 0; j < 8; j++)
            v[j] = fmaf(fmaf(v[j], scale, e1 * x1[j]), 1.f, e2 * x2[j]);
        m = mn;
    }
    for (; n < en; n += 8) {
        uint4 p1 = ((const uint4*)(d_nodesh + (size_t)n * 256))[lane];
        float2 a0 = __half22float2(*(__half2*)&p1.x);
        float2 a1 = __half22float2(*(__half2*)&p1.y);
        float2 a2 = __half22float2(*(__half2*)&p1.z);
        float2 a3 = __half22float2(*(__half2*)&p1.w);
        float x1[8] = {a0.x, a0.y, a1.x, a1.y, a2.x, a2.y, a3.x, a3.y};
        float d1 = 0.f;
        #pragma unroll
        for (int j = 0; j < 8; j++) d1 = fmaf(x1[j], qv[j], d1);
        #pragma unroll
        for (int o = 16; o; o >>= 1) d1 += __shfl_xor_sync(0xffffffffu, d1, o);
        float mn = fmaxf(m, d1);
        float scale = __expf(m - mn);
        float e1 = __expf(d1 - mn);
        ssum = ssum * scale + e1;
        #pragma unroll
        for (int j = 0; j < 8; j++) v[j] = fmaf(v[j], scale, e1 * x1[j]);
        m = mn;
    }

    if (lane == 0) { wmx[w] = m; wsx[w] = ssum; }
    {
        float4* dst = (float4*)&vsum[w][8 * lane];
        dst[0] = make_float4(v[0], v[1], v[2], v[3]);
        dst[1] = make_float4(v[4], v[5], v[6], v[7]);
    }
    __syncthreads();

    if (tid == 0) {
        float M = -3.4e38f;
        #pragma unroll
        for (int i = 0; i < 8; i++) if (wsx[i] > 0.f) M = fmaxf(M, wmx[i]);
        float S = 0.f;
        #pragma unroll
        for (int i = 0; i < 8; i++) {
            float sc = (wsx[i] > 0.f) ? __expf(wmx[i] - M) : 0.f;
            wscale[i] = sc;
            S += wsx[i] * sc;
        }
        s_inv = (S > 0.f) ? 1.f / S : 0.f;
    }
    __syncthreads();

    float acc = 0.f;
    #pragma unroll
    for (int i = 0; i < 8; i++) acc = fmaf(vsum[i][tid], wscale[i], acc);
    acc *= s_inv;

    if (final_iter) {
        dout[(size_t)g * 512 + tid] = qs[tid];
        dout[(size_t)g * 512 + 256 + tid] = acc;
    } else {
        d_X0[(size_t)g * 768 + tid] = __float2half_rn(qs[tid]);
        d_X0[(size_t)g * 768 + 256 + tid] = __float2half_rn(acc);
    }
}

// ---------------- mma.sync fp16 GEMM: gates[:, tn-tile] = X[:, ks:ks+kl] * W^T ----
// CTA tile 128(M)x64(N), 8 warps (4m x 2n), warp tile 32x32, BK=64,
// 3-stage cp.async, one sync per 64-K iter. 2 CTAs/SM.
#define ROWB 144                   // 64 halves (128 B) + 16 B pad; conflict-free ldsm
#define ARR_A (128 * ROWB)         // 18432 B
#define ARR_B (64 * ROWB)          // 9216 B
#define STG   (ARR_A + ARR_B)      // 27648 B per stage
#define SMEM_GEMM (3 * STG)        // 82944 B

__global__ __launch_bounds__(256, 2) void mma_gates(int layer, int B, int k_start, int k_len) {
    const __half* __restrict__ Ag = layer ? d_X1 : d_X0;
    const __half* __restrict__ Wg = layer ? d_W1 : d_W0;
    const int Kf = layer ? 512 : 768;

    extern __shared__ __half sm[];
    const uint32_t sbase = smem_u32(sm);

    const int tid = threadIdx.x, lane = tid & 31, warp = tid >> 5;
    const int wm = warp >> 1, wn = warp & 1;
    const int tm = blockIdx.y, tn = blockIdx.x;   // tn over 16 N-tiles of 64

    float c[2][4][4];
    #pragma unroll
    for (int i = 0; i < 2; i++)
        #pragma unroll
        for (int j = 0; j < 4; j++)
            #pragma unroll
            for (int k = 0; k < 4; k++) c[i][j][k] = 0.f;

    // cp.async mapping: A = 1024 chunks (4/thread), B = 512 chunks (2/thread)
    int rowa[4], cha[4], ara[4];
    #pragma unroll
    for (int j = 0; j < 4; j++) {
        int idx = tid + 256 * j;
        rowa[j] = idx >> 3;
        cha[j]  = idx & 7;
        int ar = tm * 128 + rowa[j]; if (ar >= B) ar = B - 1;
        ara[j] = ar;
    }
    int rowb[2], chb[2], brb[2];
    #pragma unroll
    for (int j = 0; j < 2; j++) {
        int idx = tid + 256 * j;
        rowb[j] = idx >> 3;
        chb[j]  = idx & 7;
        brb[j]  = tn * 64 + rowb[j];
    }

    const int niter = k_len >> 6;

    #define ISSUE(I, BUF) do {                                                    \
        int _k0 = k_start + ((I) << 6);                                           \
        _Pragma("unroll")                                                         \
        for (int j = 0; j < 4; j++) {                                             \
            uint32_t _d = sbase + (BUF) * STG + rowa[j] * ROWB + cha[j] * 16;     \
            cp16(_d, Ag + (size_t)ara[j] * Kf + _k0 + cha[j] * 8);                \
        }                                                                         \
        _Pragma("unroll")                                                         \
        for (int j = 0; j < 2; j++) {                                             \
            uint32_t _d = sbase + (BUF) * STG + ARR_A + rowb[j] * ROWB + chb[j] * 16; \
            cp16(_d, Wg + (size_t)brb[j] * Kf + _k0 + chb[j] * 8);                \
        }                                                                         \
        CP_COMMIT();                                                              \
    } while (0)

    ISSUE(0, 0);
    ISSUE(1, 1);

    const int m0 = wm * 32, n0 = wn * 32;
    const uint32_t a_row = m0 + (lane & 15);
    const uint32_t a_koff = (lane >> 4) * 16;
    const uint32_t b_row = n0 + (lane & 7) + ((lane >> 4) << 3);
    const uint32_t b_koff = ((lane >> 3) & 1) * 16;

    int buf = 0, nbuf = 2;
    for (int i = 0; i < niter; i++) {
        if (i + 1 < niter) CP_WAIT1(); else CP_WAIT0();
        __syncthreads();
        if (i + 2 < niter) ISSUE(i + 2, nbuf);

        uint32_t aA = sbase + buf * STG;
        uint32_t aB = aA + ARR_A;

        #pragma unroll
        for (int kk = 0; kk < 4; kk++) {
            uint32_t kb = kk * 32;
            uint32_t ah[2][4], bh[2][4];
            ldsm4(ah[0], aA + a_row * ROWB + kb + a_koff);
            ldsm4(ah[1], aA + (a_row + 16) * ROWB + kb + a_koff);
            #pragma unroll
            for (int nb = 0; nb < 2; nb++)
                ldsm4(bh[nb], aB + (b_row + nb * 16) * ROWB + kb + b_koff);
            #pragma unroll
            for (int mi = 0; mi < 2; mi++)
                #pragma unroll
                for (int nb = 0; nb < 2; nb++)
                    #pragma unroll
                    for (int h = 0; h < 2; h++) {
                        int n8 = nb * 2 + h;
                        mma16816(c[mi][n8], ah[mi], &bh[nb][h * 2]);
                    }
        }
        buf = (buf == 2) ? 0 : buf + 1;
        nbuf = (nbuf == 2) ? 0 : nbuf + 1;
    }

    // epilogue: write fp32 gates
    int g = lane >> 2, qt = lane & 3;
    #pragma unroll
    for (int mi = 0; mi < 2; mi++) {
        #pragma unroll
        for (int n8 = 0; n8 < 4; n8++) {
            int row = tm * 128 + m0 + mi * 16 + g;
            int col = tn * 64 + n0 + n8 * 8 + qt * 2;
            if (row < B)
                *(float2*)&d_gates[(size_t)row * 1024 + col] = make_float2(c[mi][n8][0], c[mi][n8][1]);
            if (row + 8 < B)
                *(float2*)&d_gates[(size_t)(row + 8) * 1024 + col] = make_float2(c[mi][n8][2], c[mi][n8][3]);
        }
    }
    #undef ISSUE
}

// ---------------- LSTM layer-0 pointwise: gates -> (h0, c0), writes fp16 inputs ----
__global__ void lstm_act0_kernel(int B) {
    int idx = blockIdx.x * blockDim.x + threadIdx.x;
    if (idx >= B * 256) return;
    int b = idx >> 8, t = idx & 255;
    const float* gr = d_gates + (size_t)b * 1024;

    float gi = gr[t]       + d_b0[t];
    float gf = gr[t + 256] + d_b0[t + 256];
    float gg = gr[t + 512] + d_b0[t + 512];
    float go = gr[t + 768] + d_b0[t + 768];

    float si = 1.f / (1.f + expf(-gi));
    float sf = 1.f / (1.f + expf(-gf));
    float tg = tanhf(gg);
    float so = 1.f / (1.f + expf(-go));

    float cn = sf * d_c0[idx] + si * tg;
    d_c0[idx] = cn;
    float hn = so * tanhf(cn);

    __half h = __float2half_rn(hn);
    d_X0[(size_t)b * 768 + 512 + t] = h;
    d_X1[(size_t)b * 512 + t]       = h;
}

// ---------------- host launcher ----------------
extern "C" void kernel_launch(void* const* d_in, const int* in_sizes, int n_in,
                              void* d_out, int out_size) {
    const float* nodes = (const float*)d_in[0];
    const void*  gid   = d_in[1];
    int N = in_sizes[1];

    int wbase = (in_sizes[2] == 1) ? 3 : 2;
    const float* Wih0 = (const float*)d_in[wbase + 0];
    const float* Whh0 = (const float*)d_in[wbase + 1];
    const float* bih0 = (const float*)d_in[wbase + 2];
    const float* bhh0 = (const float*)d_in[wbase + 3];
    const float* Wih1 = (const float*)d_in[wbase + 4];
    const float* Whh1 = (const float*)d_in[wbase + 5];
    const float* bih1 = (const float*)d_in[wbase + 6];
    const float* bhh1 = (const float*)d_in[wbase + 7];

    int B = out_size / (2 * Hh);
    float* out = (float*)d_out;

    cudaFuncSetAttribute(mma_gates, cudaFuncAttributeMaxDynamicSharedMemorySize, SMEM_GEMM);

    starts_kernel<<<(B + 1 + 255) / 256, 256>>>((const int*)gid, N, B);
    int pack_n = (B * 768 > 1024 * 768) ? B * 768 : 1024 * 768;
    pack_kernel<<<(pack_n + 255) / 256, 256>>>(Wih0, Whh0, bih0, bhh0,
                                               Wih1, Whh1, bih1, bhh1, B);

    dim3 gemm_grid(1024 / 64, (B + 127) / 128);   // 16 x 16 = 256 CTAs
    const int M_ITERS = 6;
    for (int i = 0; i < M_ITERS; i++) {
        int final_iter = (i == M_ITERS - 1) ? 1 : 0;
        if (i == 0) {
            convert_mean_kernel<<<B, 256>>>(nodes);
        } else {
            attention_kernel<<<B, 256>>>(out, final_iter);
        }
        if (!final_iter) {
            if (i == 0) {
                mma_gates<<<gemm_grid, 256, SMEM_GEMM>>>(0, B, 256, 256);
                lstm_act0_kernel<<<(B * 256 + 255) / 256, 256>>>(B);
                mma_gates<<<gemm_grid, 256, SMEM_GEMM>>>(1, B, 0, 256);
            } else {
                mma_gates<<<gemm_grid, 256, SMEM_GEMM>>>(0, B, 0, 768);
                lstm_act0_kernel<<<(B * 256 + 255) / 256, 256>>>(B);
                mma_gates<<<gemm_grid, 256, SMEM_GEMM>>>(1, B, 0, 512);
            }
        }
    }
}

// round 17
// speedup vs baseline: 1.0211x; 1.0211x over previous
#include <cuda_runtime.h>
#include <cuda_fp16.h>
#include <math.h>
#include <stdint.h>

#define Hh 256
#define NMAX 262144
#define BMAX 4096

// ---------------- device scratch (no allocations allowed) ----------------
__device__ int    d_starts[BMAX + 1];
__device__ float  d_gates[BMAX * 1024];
__device__ float  d_c0[BMAX * 256];
__device__ float  d_c1[BMAX * 256];
__device__ __half d_nodesh[(size_t)NMAX * 256];   // fp16 copy of nodes
// fp16 operands
__device__ __half d_X0[BMAX * 768];          // [q_star(512)|h0(256)]
__device__ __half d_X1[BMAX * 512];          // [h0(256)|h1(256)]
__device__ __half d_W0[1024 * 768];          // [Wih0|Whh0]
__device__ __half d_W1[1024 * 512];          // [Wih1|Whh1]
__device__ float  d_b0[1024], d_b1[1024];

// ---------------- small helpers ----------------
__device__ __forceinline__ uint32_t smem_u32(const void* p) {
    uint32_t a;
    asm("{ .reg .u64 t; cvta.to.shared.u64 t, %1; cvt.u32.u64 %0, t; }" : "=r"(a) : "l"(p));
    return a;
}
__device__ __forceinline__ void cp16(uint32_t dst, const void* src) {
    asm volatile("cp.async.cg.shared.global [%0], [%1], 16;" :: "r"(dst), "l"(src));
}
#define CP_COMMIT() asm volatile("cp.async.commit_group;" ::: "memory")
#define CP_WAIT1()  asm volatile("cp.async.wait_group 1;" ::: "memory")
#define CP_WAIT0()  asm volatile("cp.async.wait_group 0;" ::: "memory")

__device__ __forceinline__ void ldsm4(uint32_t* r, uint32_t addr) {
    asm volatile("ldmatrix.sync.aligned.m8n8.x4.shared.b16 {%0,%1,%2,%3}, [%4];"
                 : "=r"(r[0]), "=r"(r[1]), "=r"(r[2]), "=r"(r[3]) : "r"(addr));
}
__device__ __forceinline__ void mma16816(float* c, const uint32_t* a, const uint32_t* b) {
    asm volatile(
        "mma.sync.aligned.m16n8k16.row.col.f32.f16.f16.f32 "
        "{%0,%1,%2,%3},{%4,%5,%6,%7},{%8,%9},{%0,%1,%2,%3};"
        : "+f"(c[0]), "+f"(c[1]), "+f"(c[2]), "+f"(c[3])
        : "r"(a[0]), "r"(a[1]), "r"(a[2]), "r"(a[3]), "r"(b[0]), "r"(b[1]));
}
__device__ __forceinline__ void cvt8(const uint4& p, float* x) {
    float2 f0 = __half22float2(*(__half2*)&p.x);
    float2 f1 = __half22float2(*(__half2*)&p.y);
    float2 f2 = __half22float2(*(__half2*)&p.z);
    float2 f3 = __half22float2(*(__half2*)&p.w);
    x[0] = f0.x; x[1] = f0.y; x[2] = f1.x; x[3] = f1.y;
    x[4] = f2.x; x[5] = f2.y; x[6] = f3.x; x[7] = f3.y;
}

// ---------------- starts (with inline graph_id dtype sniff) ----------------
__global__ void starts_kernel(const int* p, int N, int B) {
    int g = blockIdx.x * blockDim.x + threadIdx.x;
    if (g > B) return;
    int is64 = 1;
    for (int j = 0; j < 8; j++) {
        int idx = N - 1 - 2 * j;
        if (idx < 1) break;
        if ((idx & 1) == 0) idx--;
        if (idx >= 1 && p[idx] != 0) is64 = 0;
    }
    const long long* p64 = (const long long*)p;
    int lo = 0, hi = N;
    while (lo < hi) {
        int mid = (lo + hi) >> 1;
        int v = is64 ? (int)p64[mid] : p[mid];
        if (v < g) lo = mid + 1; else hi = mid;
    }
    d_starts[g] = lo;
}

// ---------------- pack weights (fp16) + summed biases + c-state init ----------------
__global__ void pack_kernel(const float* __restrict__ Wih0, const float* __restrict__ Whh0,
                            const float* __restrict__ bih0, const float* __restrict__ bhh0,
                            const float* __restrict__ Wih1, const float* __restrict__ Whh1,
                            const float* __restrict__ bih1, const float* __restrict__ bhh1,
                            int B) {
    int i = blockIdx.x * blockDim.x + threadIdx.x;
    if (i < 1024 * 768) {
        int j = i / 768, k = i % 768;
        float v = (k < 512) ? Wih0[j * 512 + k] : Whh0[j * 256 + (k - 512)];
        d_W0[i] = __float2half_rn(v);
    }
    if (i < 1024 * 512) {
        int j = i / 512, k = i % 512;
        float v = (k < 256) ? Wih1[j * 256 + k] : Whh1[j * 256 + (k - 256)];
        d_W1[i] = __float2half_rn(v);
    }
    if (i < 1024) {
        d_b0[i] = bih0[i] + bhh0[i];
        d_b1[i] = bih1[i] + bhh1[i];
    }
    if (i < B * 256) { d_c0[i] = 0.f; d_c1[i] = 0.f; }
}

// ---------------- iteration 0: convert nodes->fp16 AND compute mean readout ----
__global__ void convert_mean_kernel(const float* __restrict__ nodes) {
    int g = blockIdx.x;
    int s = d_starts[g], en = d_starts[g + 1];
    int len = en - s;
    __shared__ float vsum[8][256];
    int tid = threadIdx.x, lane = tid & 31, w = tid >> 5;

    float v[8];
    #pragma unroll
    for (int j = 0; j < 8; j++) v[j] = 0.f;

    for (int n = s + w; n < en; n += 8) {
        const float4* rp = (const float4*)(nodes + (size_t)n * 256);
        float4 a = rp[2 * lane], b = rp[2 * lane + 1];
        __half2 h0 = __floats2half2_rn(a.x, a.y);
        __half2 h1 = __floats2half2_rn(a.z, a.w);
        __half2 h2 = __floats2half2_rn(b.x, b.y);
        __half2 h3 = __floats2half2_rn(b.z, b.w);
        uint4 pk;
        pk.x = *(uint32_t*)&h0; pk.y = *(uint32_t*)&h1;
        pk.z = *(uint32_t*)&h2; pk.w = *(uint32_t*)&h3;
        ((uint4*)(d_nodesh + (size_t)n * 256))[lane] = pk;
        v[0] += a.x; v[1] += a.y; v[2] += a.z; v[3] += a.w;
        v[4] += b.x; v[5] += b.y; v[6] += b.z; v[7] += b.w;
    }
    {
        float4* dst = (float4*)&vsum[w][8 * lane];
        dst[0] = make_float4(v[0], v[1], v[2], v[3]);
        dst[1] = make_float4(v[4], v[5], v[6], v[7]);
    }
    __syncthreads();

    float inv = (len > 0) ? 1.f / (float)len : 0.f;
    float acc = 0.f;
    #pragma unroll
    for (int i = 0; i < 8; i++) acc += vsum[i][tid];
    acc *= inv;

    d_X0[(size_t)g * 768 + tid] = __float2half_rn(0.f);
    d_X0[(size_t)g * 768 + 256 + tid] = __float2half_rn(acc);
}

// ---------------- attention (iters 1..5): fused act1 prologue + online softmax ----
// 4-row unrolled: each warp handles rows n, n+8, n+16, n+24 per iteration.
__global__ void attention_kernel(float* __restrict__ dout, int final_iter) {
    int g = blockIdx.x;
    int s = d_starts[g], en = d_starts[g + 1];
    __shared__ float qs[256];
    __shared__ float vsum[8][256];
    __shared__ float wmx[8], wsx[8], wscale[8];
    __shared__ float s_inv;
    int tid = threadIdx.x, lane = tid & 31, w = tid >> 5;

    // ---- fused LSTM layer-1 activation: gates -> (h1, c1); q = h1 ----
    {
        const float* gr = d_gates + (size_t)g * 1024;
        float gi = gr[tid]       + d_b1[tid];
        float gf = gr[tid + 256] + d_b1[tid + 256];
        float gg = gr[tid + 512] + d_b1[tid + 512];
        float go = gr[tid + 768] + d_b1[tid + 768];
        float si = 1.f / (1.f + expf(-gi));
        float sf = 1.f / (1.f + expf(-gf));
        float tg = tanhf(gg);
        float so = 1.f / (1.f + expf(-go));
        size_t ci = (size_t)g * 256 + tid;
        float cn = sf * d_c1[ci] + si * tg;
        d_c1[ci] = cn;
        float hn = so * tanhf(cn);
        qs[tid] = hn;
        d_X1[(size_t)g * 512 + 256 + tid] = __float2half_rn(hn);
    }
    __syncthreads();

    float qv[8];
    #pragma unroll
    for (int j = 0; j < 8; j++) qv[j] = qs[8 * lane + j];

    float m = -3.4e38f, ssum = 0.f;
    float v[8];
    #pragma unroll
    for (int j = 0; j < 8; j++) v[j] = 0.f;

    const uint4* nb = (const uint4*)d_nodesh;   // 32 uint4 per 256-half row
    int n = s + w;

    // ---- 4-row main loop ----
    for (; n + 24 < en; n += 32) {
        uint4 p1 = nb[(size_t)n * 32 + lane];
        uint4 p2 = nb[(size_t)(n + 8) * 32 + lane];
        uint4 p3 = nb[(size_t)(n + 16) * 32 + lane];
        uint4 p4 = nb[(size_t)(n + 24) * 32 + lane];
        float x1[8], x2[8], x3[8], x4[8];
        cvt8(p1, x1); cvt8(p2, x2); cvt8(p3, x3); cvt8(p4, x4);

        float d1 = 0.f, d2 = 0.f, d3 = 0.f, d4 = 0.f;
        #pragma unroll
        for (int j = 0; j < 8; j++) {
            d1 = fmaf(x1[j], qv[j], d1);
            d2 = fmaf(x2[j], qv[j], d2);
            d3 = fmaf(x3[j], qv[j], d3);
            d4 = fmaf(x4[j], qv[j], d4);
        }
        #pragma unroll
        for (int o = 16; o; o >>= 1) {
            d1 += __shfl_xor_sync(0xffffffffu, d1, o);
            d2 += __shfl_xor_sync(0xffffffffu, d2, o);
            d3 += __shfl_xor_sync(0xffffffffu, d3, o);
            d4 += __shfl_xor_sync(0xffffffffu, d4, o);
        }

        float mn = fmaxf(m, fmaxf(fmaxf(d1, d2), fmaxf(d3, d4)));
        float scale = __expf(m - mn);
        float e1 = __expf(d1 - mn);
        float e2 = __expf(d2 - mn);
        float e3 = __expf(d3 - mn);
        float e4 = __expf(d4 - mn);
        ssum = ssum * scale + ((e1 + e2) + (e3 + e4));
        #pragma unroll
        for (int j = 0; j < 8; j++) {
            float t = fmaf(v[j], scale, e1 * x1[j]);
            t = fmaf(e2, x2[j], t);
            t = fmaf(e3, x3[j], t);
            v[j] = fmaf(e4, x4[j], t);
        }
        m = mn;
    }
    // ---- 2-row tail ----
    for (; n + 8 < en; n += 16) {
        uint4 p1 = nb[(size_t)n * 32 + lane];
        uint4 p2 = nb[(size_t)(n + 8) * 32 + lane];
        float x1[8], x2[8];
        cvt8(p1, x1); cvt8(p2, x2);
        float d1 = 0.f, d2 = 0.f;
        #pragma unroll
        for (int j = 0; j < 8; j++) {
            d1 = fmaf(x1[j], qv[j], d1);
            d2 = fmaf(x2[j], qv[j], d2);
        }
        #pragma unroll
        for (int o = 16; o; o >>= 1) {
            d1 += __shfl_xor_sync(0xffffffffu, d1, o);
            d2 += __shfl_xor_sync(0xffffffffu, d2, o);
        }
        float mn = fmaxf(m, fmaxf(d1, d2));
        float scale = __expf(m - mn);
        float e1 = __expf(d1 - mn);
        float e2 = __expf(d2 - mn);
        ssum = ssum * scale + e1 + e2;
        #pragma unroll
        for (int j = 0; j < 8; j++) {
            float t = fmaf(v[j], scale, e1 * x1[j]);
            v[j] = fmaf(e2, x2[j], t);
        }
        m = mn;
    }
    // ---- 1-row tail ----
    for (; n < en; n += 8) {
        uint4 p1 = nb[(size_t)n * 32 + lane];
        float x1[8];
        cvt8(p1, x1);
        float d1 = 0.f;
        #pragma unroll
        for (int j = 0; j < 8; j++) d1 = fmaf(x1[j], qv[j], d1);
        #pragma unroll
        for (int o = 16; o; o >>= 1) d1 += __shfl_xor_sync(0xffffffffu, d1, o);
        float mn = fmaxf(m, d1);
        float scale = __expf(m - mn);
        float e1 = __expf(d1 - mn);
        ssum = ssum * scale + e1;
        #pragma unroll
        for (int j = 0; j < 8; j++) v[j] = fmaf(v[j], scale, e1 * x1[j]);
        m = mn;
    }

    if (lane == 0) { wmx[w] = m; wsx[w] = ssum; }
    {
        float4* dst = (float4*)&vsum[w][8 * lane];
        dst[0] = make_float4(v[0], v[1], v[2], v[3]);
        dst[1] = make_float4(v[4], v[5], v[6], v[7]);
    }
    __syncthreads();

    if (tid == 0) {
        float M = -3.4e38f;
        #pragma unroll
        for (int i = 0; i < 8; i++) if (wsx[i] > 0.f) M = fmaxf(M, wmx[i]);
        float S = 0.f;
        #pragma unroll
        for (int i = 0; i < 8; i++) {
            float sc = (wsx[i] > 0.f) ? __expf(wmx[i] - M) : 0.f;
            wscale[i] = sc;
            S += wsx[i] * sc;
        }
        s_inv = (S > 0.f) ? 1.f / S : 0.f;
    }
    __syncthreads();

    float acc = 0.f;
    #pragma unroll
    for (int i = 0; i < 8; i++) acc = fmaf(vsum[i][tid], wscale[i], acc);
    acc *= s_inv;

    if (final_iter) {
        dout[(size_t)g * 512 + tid] = qs[tid];
        dout[(size_t)g * 512 + 256 + tid] = acc;
    } else {
        d_X0[(size_t)g * 768 + tid] = __float2half_rn(qs[tid]);
        d_X0[(size_t)g * 768 + 256 + tid] = __float2half_rn(acc);
    }
}

// ---------------- mma.sync fp16 GEMM (R14 config): gates = X[:,ks:ks+kl] * W^T ----
// CTA tile 128x128, 8 warps (4m x 2n), warp tile 32x64, BK=64, 3-stage cp.async.
#define ROWB 144                   // 64 halves (128 B) + 16 B pad; conflict-free ldsm
#define ARR  (128 * ROWB)          // 18432 B per array
#define STG  (2 * ARR)             // 36864 B per stage (A, B)
#define SMEM_GEMM (3 * STG)        // 110592 B

__global__ __launch_bounds__(256, 1) void mma_gates(int layer, int B, int k_start, int k_len) {
    const __half* __restrict__ Ag = layer ? d_X1 : d_X0;
    const __half* __restrict__ Wg = layer ? d_W1 : d_W0;
    const int Kf = layer ? 512 : 768;

    extern __shared__ __half sm[];
    const uint32_t sbase = smem_u32(sm);

    const int tid = threadIdx.x, lane = tid & 31, warp = tid >> 5;
    const int wm = warp >> 1, wn = warp & 1;
    const int tm = blockIdx.y, tn = blockIdx.x;

    float c[2][8][4];
    #pragma unroll
    for (int i = 0; i < 2; i++)
        #pragma unroll
        for (int j = 0; j < 8; j++)
            #pragma unroll
            for (int k = 0; k < 4; k++) c[i][j][k] = 0.f;

    int rowj[4], chj[4], arj[4], brj[4];
    #pragma unroll
    for (int j = 0; j < 4; j++) {
        int idx = tid + 256 * j;
        rowj[j] = idx >> 3;
        chj[j]  = idx & 7;
        int ar = tm * 128 + rowj[j]; if (ar >= B) ar = B - 1;
        arj[j] = ar;
        brj[j] = tn * 128 + rowj[j];
    }

    const int niter = k_len >> 6;

    #define ISSUE(I, BUF) do {                                                    \
        int _k0 = k_start + ((I) << 6);                                           \
        _Pragma("unroll")                                                         \
        for (int j = 0; j < 4; j++) {                                             \
            uint32_t _d = sbase + (BUF) * STG + rowj[j] * ROWB + chj[j] * 16;     \
            cp16(_d,       Ag + (size_t)arj[j] * Kf + _k0 + chj[j] * 8);          \
            cp16(_d + ARR, Wg + (size_t)brj[j] * Kf + _k0 + chj[j] * 8);          \
        }                                                                         \
        CP_COMMIT();                                                              \
    } while (0)

    ISSUE(0, 0);
    ISSUE(1, 1);

    const int m0 = wm * 32, n0 = wn * 64;
    const uint32_t a_row = m0 + (lane & 15);
    const uint32_t a_koff = (lane >> 4) * 16;
    const uint32_t b_row = n0 + (lane & 7) + ((lane >> 4) << 3);
    const uint32_t b_koff = ((lane >> 3) & 1) * 16;

    int buf = 0, nbuf = 2;
    for (int i = 0; i < niter; i++) {
        if (i + 1 < niter) CP_WAIT1(); else CP_WAIT0();
        __syncthreads();
        if (i + 2 < niter) ISSUE(i + 2, nbuf);

        uint32_t aA = sbase + buf * STG;
        uint32_t aB = aA + ARR;

        #pragma unroll
        for (int kk = 0; kk < 4; kk++) {
            uint32_t kb = kk * 32;
            uint32_t ah[2][4], bh[4][4];
            ldsm4(ah[0], aA + a_row * ROWB + kb + a_koff);
            ldsm4(ah[1], aA + (a_row + 16) * ROWB + kb + a_koff);
            #pragma unroll
            for (int nb = 0; nb < 4; nb++)
                ldsm4(bh[nb], aB + (b_row + nb * 16) * ROWB + kb + b_koff);
            #pragma unroll
            for (int mi = 0; mi < 2; mi++)
                #pragma unroll
                for (int nb = 0; nb < 4; nb++)
                    #pragma unroll
                    for (int h = 0; h < 2; h++) {
                        int n8 = nb * 2 + h;
                        mma16816(c[mi][n8], ah[mi], &bh[nb][h * 2]);
                    }
        }
        buf = (buf == 2) ? 0 : buf + 1;
        nbuf = (nbuf == 2) ? 0 : nbuf + 1;
    }

    int g = lane >> 2, qt = lane & 3;
    #pragma unroll
    for (int mi = 0; mi < 2; mi++) {
        #pragma unroll
        for (int n8 = 0; n8 < 8; n8++) {
            int row = tm * 128 + m0 + mi * 16 + g;
            int col = tn * 128 + n0 + n8 * 8 + qt * 2;
            if (row < B)
                *(float2*)&d_gates[(size_t)row * 1024 + col] = make_float2(c[mi][n8][0], c[mi][n8][1]);
            if (row + 8 < B)
                *(float2*)&d_gates[(size_t)(row + 8) * 1024 + col] = make_float2(c[mi][n8][2], c[mi][n8][3]);
        }
    }
    #undef ISSUE
}

// ---------------- LSTM layer-0 pointwise: gates -> (h0, c0), writes fp16 inputs ----
__global__ void lstm_act0_kernel(int B) {
    int idx = blockIdx.x * blockDim.x + threadIdx.x;
    if (idx >= B * 256) return;
    int b = idx >> 8, t = idx & 255;
    const float* gr = d_gates + (size_t)b * 1024;

    float gi = gr[t]       + d_b0[t];
    float gf = gr[t + 256] + d_b0[t + 256];
    float gg = gr[t + 512] + d_b0[t + 512];
    float go = gr[t + 768] + d_b0[t + 768];

    float si = 1.f / (1.f + expf(-gi));
    float sf = 1.f / (1.f + expf(-gf));
    float tg = tanhf(gg);
    float so = 1.f / (1.f + expf(-go));

    float cn = sf * d_c0[idx] + si * tg;
    d_c0[idx] = cn;
    float hn = so * tanhf(cn);

    __half h = __float2half_rn(hn);
    d_X0[(size_t)b * 768 + 512 + t] = h;
    d_X1[(size_t)b * 512 + t]       = h;
}

// ---------------- host launcher ----------------
extern "C" void kernel_launch(void* const* d_in, const int* in_sizes, int n_in,
                              void* d_out, int out_size) {
    const float* nodes = (const float*)d_in[0];
    const void*  gid   = d_in[1];
    int N = in_sizes[1];

    int wbase = (in_sizes[2] == 1) ? 3 : 2;
    const float* Wih0 = (const float*)d_in[wbase + 0];
    const float* Whh0 = (const float*)d_in[wbase + 1];
    const float* bih0 = (const float*)d_in[wbase + 2];
    const float* bhh0 = (const float*)d_in[wbase + 3];
    const float* Wih1 = (const float*)d_in[wbase + 4];
    const float* Whh1 = (const float*)d_in[wbase + 5];
    const float* bih1 = (const float*)d_in[wbase + 6];
    const float* bhh1 = (const float*)d_in[wbase + 7];

    int B = out_size / (2 * Hh);
    float* out = (float*)d_out;

    cudaFuncSetAttribute(mma_gates, cudaFuncAttributeMaxDynamicSharedMemorySize, SMEM_GEMM);

    starts_kernel<<<(B + 1 + 255) / 256, 256>>>((const int*)gid, N, B);
    int pack_n = (B * 768 > 1024 * 768) ? B * 768 : 1024 * 768;
    pack_kernel<<<(pack_n + 255) / 256, 256>>>(Wih0, Whh0, bih0, bhh0,
                                               Wih1, Whh1, bih1, bhh1, B);

    dim3 gemm_grid(1024 / 128, (B + 127) / 128);
    const int M_ITERS = 6;
    for (int i = 0; i < M_ITERS; i++) {
        int final_iter = (i == M_ITERS - 1) ? 1 : 0;
        if (i == 0) {
            convert_mean_kernel<<<B, 256>>>(nodes);
        } else {
            attention_kernel<<<B, 256>>>(out, final_iter);
        }
        if (!final_iter) {
            if (i == 0) {
                mma_gates<<<gemm_grid, 256, SMEM_GEMM>>>(0, B, 256, 256);
                lstm_act0_kernel<<<(B * 256 + 255) / 256, 256>>>(B);
                mma_gates<<<gemm_grid, 256, SMEM_GEMM>>>(1, B, 0, 256);
            } else {
                mma_gates<<<gemm_grid, 256, SMEM_GEMM>>>(0, B, 0, 768);
                lstm_act0_kernel<<<(B * 256 + 255) / 256, 256>>>(B);
                mma_gates<<<gemm_grid, 256, SMEM_GEMM>>>(1, B, 0, 512);
            }
        }
    }
}